// round 13
// baseline (speedup 1.0000x reference)
#include <cuda_runtime.h>
#include <math.h>
#include <cstdint>

#define D_MODEL 1024
#define NHEAD   16
#define DHEAD   64
#define BATCH   2
#define SEQ     2048
#define M_TOTAL (BATCH*SEQ)

// Scratch (allocation-free rule: __device__ globals).
__device__ float g_q[M_TOTAL*D_MODEL];
__device__ float g_k[M_TOTAL*D_MODEL];
__device__ float g_v[M_TOTAL*D_MODEL];
__device__ float g_attn[M_TOTAL*D_MODEL];

__device__ __forceinline__ uint32_t f2tf32(float x) {
    uint32_t r; asm("cvt.rna.tf32.f32 %0, %1;" : "=r"(r) : "f"(x));
    return r;
}

__device__ __forceinline__ void mma_tf32(float c[4], const uint32_t a[4], const uint32_t b[2]) {
    asm volatile(
        "mma.sync.aligned.m16n8k8.row.col.f32.tf32.tf32.f32 "
        "{%0,%1,%2,%3}, {%4,%5,%6,%7}, {%8,%9}, {%0,%1,%2,%3};"
        : "+f"(c[0]), "+f"(c[1]), "+f"(c[2]), "+f"(c[3])
        : "r"(a[0]), "r"(a[1]), "r"(a[2]), "r"(a[3]), "r"(b[0]), "r"(b[1]));
}

// ---------------------------------------------------------------------------
// tf32 mma.sync GEMM (R8 single-buffer structure) with PAIR-INTERLEAVED smem:
// k-pair (j, j+4) stored adjacent inside each 8-slot group, rotated by
// (2*(row&3)) within the group. Every fragment load = one LDS.64
// (96 -> 48 LDS per warp-ktile). STS pattern conflict-free by the rotation.
// ---------------------------------------------------------------------------
#define PITCH 40

__global__ void __launch_bounds__(256) gemm_tf32_kernel(
    const float* __restrict__ X,
    const float* __restrict__ Wq, const float* __restrict__ Wk,
    const float* __restrict__ Wv, const float* __restrict__ Wo,
    const int*   __restrict__ pos,
    float* __restrict__ dout,
    int mode_base)
{
    __shared__ __align__(16) uint32_t As[128*PITCH];
    __shared__ __align__(16) uint32_t Bs[128*PITCH];

    const int mode = mode_base + blockIdx.z;
    const float* A = (mode == 3) ? g_attn : X;
    const float* W = (mode == 0) ? Wq : (mode == 1) ? Wk : (mode == 2) ? Wv : Wo;
    float* out = (mode == 0) ? g_q : (mode == 1) ? g_k : (mode == 2) ? g_v : dout;
    const bool rope = (mode <= 1);

    const int tid  = threadIdx.x;
    const int warp = tid >> 5;
    const int lane = tid & 31;
    const int gr   = lane >> 2;
    const int tig  = lane & 3;
    const int wm   = warp & 3;
    const int wn   = warp >> 2;
    const int m0   = blockIdx.y * 128;
    const int n0   = blockIdx.x * 128;

    float acc[2][8][4];
    #pragma unroll
    for (int mf = 0; mf < 2; mf++)
        #pragma unroll
        for (int nf = 0; nf < 8; nf++)
            #pragma unroll
            for (int c = 0; c < 4; c++) acc[mf][nf][c] = 0.f;

    const float* Ap = A + (size_t)m0 * D_MODEL;
    const float* Wp = W + (size_t)n0 * D_MODEL;

    // Loader: thread covers (row, group g) -> 8 k-values (g*8 .. g*8+7).
    const int lrow = tid >> 2;      // 0..63 (+64 for u=1)
    const int lg   = tid & 3;       // k-group 0..3

    // Per-thread fragment-read rotation (row parity class = gr&3)
    const int roff = (2*(gr & 3)) & 7;

    float4 pa[2][2], pb[2][2];
    #pragma unroll
    for (int u = 0; u < 2; u++) {
        int row = lrow + u * 64;
        pa[u][0] = *(const float4*)(Ap + (size_t)row * D_MODEL + lg*8);
        pa[u][1] = *(const float4*)(Ap + (size_t)row * D_MODEL + lg*8 + 4);
        pb[u][0] = *(const float4*)(Wp + (size_t)row * D_MODEL + lg*8);
        pb[u][1] = *(const float4*)(Wp + (size_t)row * D_MODEL + lg*8 + 4);
    }

    for (int kt = 0; kt < 32; kt++) {
        // STS prefetched tile: pairs (k, k+4) as uint2, rotated within group.
        #pragma unroll
        for (int u = 0; u < 2; u++) {
            int row  = lrow + u * 64;
            int base = row * PITCH + lg * 8;
            int rot  = (2*(row & 3));
            *(uint2*)&As[base + ((0 + rot) & 7)] = make_uint2(f2tf32(pa[u][0].x), f2tf32(pa[u][1].x));
            *(uint2*)&As[base + ((2 + rot) & 7)] = make_uint2(f2tf32(pa[u][0].y), f2tf32(pa[u][1].y));
            *(uint2*)&As[base + ((4 + rot) & 7)] = make_uint2(f2tf32(pa[u][0].z), f2tf32(pa[u][1].z));
            *(uint2*)&As[base + ((6 + rot) & 7)] = make_uint2(f2tf32(pa[u][0].w), f2tf32(pa[u][1].w));
            *(uint2*)&Bs[base + ((0 + rot) & 7)] = make_uint2(f2tf32(pb[u][0].x), f2tf32(pb[u][1].x));
            *(uint2*)&Bs[base + ((2 + rot) & 7)] = make_uint2(f2tf32(pb[u][0].y), f2tf32(pb[u][1].y));
            *(uint2*)&Bs[base + ((4 + rot) & 7)] = make_uint2(f2tf32(pb[u][0].z), f2tf32(pb[u][1].z));
            *(uint2*)&Bs[base + ((6 + rot) & 7)] = make_uint2(f2tf32(pb[u][0].w), f2tf32(pb[u][1].w));
        }
        __syncthreads();

        if (kt < 31) {
            const int kn = (kt + 1) * 32;
            #pragma unroll
            for (int u = 0; u < 2; u++) {
                int row = lrow + u * 64;
                pa[u][0] = *(const float4*)(Ap + (size_t)row * D_MODEL + kn + lg*8);
                pa[u][1] = *(const float4*)(Ap + (size_t)row * D_MODEL + kn + lg*8 + 4);
                pb[u][0] = *(const float4*)(Wp + (size_t)row * D_MODEL + kn + lg*8);
                pb[u][1] = *(const float4*)(Wp + (size_t)row * D_MODEL + kn + lg*8 + 4);
            }
        }

        #pragma unroll
        for (int ks = 0; ks < 4; ks++) {
            const int kb = ks * 8;
            const int fo = kb + ((2*tig + roff) & 7);
            uint32_t b[8][2];
            #pragma unroll
            for (int nf = 0; nf < 8; nf++) {
                int n = wn*64 + nf*8 + gr;
                uint2 bv = *(const uint2*)&Bs[n * PITCH + fo];
                b[nf][0] = bv.x; b[nf][1] = bv.y;
            }
            uint32_t a[2][4];
            #pragma unroll
            for (int mf = 0; mf < 2; mf++) {
                int m = wm*32 + mf*16 + gr;
                uint2 a02 = *(const uint2*)&As[m * PITCH + fo];
                uint2 a13 = *(const uint2*)&As[(m+8) * PITCH + fo];
                a[mf][0] = a02.x; a[mf][2] = a02.y;
                a[mf][1] = a13.x; a[mf][3] = a13.y;
            }
            #pragma unroll
            for (int mf = 0; mf < 2; mf++)
                #pragma unroll
                for (int nf = 0; nf < 8; nf++)
                    mma_tf32(acc[mf][nf], a[mf], b[nf]);
        }
        __syncthreads();
    }

    float invf[8];
    if (rope) {
        #pragma unroll
        for (int nf = 0; nf < 8; nf++) {
            int dh = (nf*8 + 2*tig) & 63;
            invf[nf] = 1.0f / powf(10000.0f, (float)dh * (1.0f/64.0f));
        }
    }

    #pragma unroll
    for (int mf = 0; mf < 2; mf++) {
        int m_lo = m0 + wm*32 + mf*16 + gr;
        int m_hi = m_lo + 8;
        float fp_lo = 0.f, fp_hi = 0.f;
        if (rope) {
            fp_lo = (float)pos[m_lo & (SEQ-1)];
            fp_hi = (float)pos[m_hi & (SEQ-1)];
        }
        #pragma unroll
        for (int nf = 0; nf < 8; nf++) {
            int n = n0 + wn*64 + nf*8 + 2*tig;
            float v0 = acc[mf][nf][0], v1 = acc[mf][nf][1];
            float v2 = acc[mf][nf][2], v3 = acc[mf][nf][3];
            if (rope) {
                float c0, s0, c1, s1;
                sincosf(fp_lo * invf[nf], &s0, &c0);
                sincosf(fp_hi * invf[nf], &s1, &c1);
                float r0 = v0*c0 - v1*s0, r1 = v1*c0 + v0*s0;
                float r2 = v2*c1 - v3*s1, r3 = v3*c1 + v2*s1;
                v0 = r0; v1 = r1; v2 = r2; v3 = r3;
            }
            *(float2*)(out + (size_t)m_lo * D_MODEL + n) = make_float2(v0, v1);
            *(float2*)(out + (size_t)m_hi * D_MODEL + n) = make_float2(v2, v3);
        }
    }
}

// ---------------------------------------------------------------------------
// Flash attention (R12 version — V gmem loads deferred past QK^T MMAs; kept).
// ---------------------------------------------------------------------------
#define PK  68
#define PVP 72

__global__ void __launch_bounds__(128) attn_mma_kernel()
{
    __shared__ float sK[64*PK];   // K tile (pre-rounded tf32); reused as P tile
    __shared__ float sV[64*PVP];  // V tile (pre-rounded tf32)

    const int tid  = threadIdx.x;
    const int warp = tid >> 5;
    const int lane = tid & 31;
    const int gr   = lane >> 2;
    const int tig  = lane & 3;
    const int qt   = gridDim.x - 1 - blockIdx.x;   // longest tiles first
    const int bh   = blockIdx.y;
    const int q0   = qt * 64;
    const int b    = bh >> 4;
    const int h    = bh & 15;

    const float* Qg = g_q + (size_t)b*SEQ*D_MODEL + h*DHEAD;
    const float* Kg = g_k + (size_t)b*SEQ*D_MODEL + h*DHEAD;
    const float* Vg = g_v + (size_t)b*SEQ*D_MODEL + h*DHEAD;

    #pragma unroll
    for (int u = 0; u < 8; u++) {
        int f   = tid + u*128;
        int row = f >> 4;
        int c   = (f & 15) << 2;
        float4 q = *(const float4*)(Qg + (size_t)(q0+row)*D_MODEL + c);
        q.x *= 0.125f; q.y *= 0.125f; q.z *= 0.125f; q.w *= 0.125f;
        *(float4*)&sK[row*PK + c] = q;
    }
    __syncthreads();

    const int r0l = warp*16 + gr;
    const int r1l = r0l + 8;

    uint32_t qh[8][4];
    #pragma unroll
    for (int kb = 0; kb < 8; kb++) {
        qh[kb][0] = f2tf32(sK[r0l*PK + kb*8 + tig]);
        qh[kb][1] = f2tf32(sK[r1l*PK + kb*8 + tig]);
        qh[kb][2] = f2tf32(sK[r0l*PK + kb*8 + tig + 4]);
        qh[kb][3] = f2tf32(sK[r1l*PK + kb*8 + tig + 4]);
    }

    float m0 = -INFINITY, m1 = -INFINITY, l0 = 0.f, l1 = 0.f;
    float acc[8][4];
    #pragma unroll
    for (int nf = 0; nf < 8; nf++)
        #pragma unroll
        for (int c = 0; c < 4; c++) acc[nf][c] = 0.f;

    const int lrow = tid >> 4;
    const int lcol = (tid & 15) << 2;

    for (int kt = 0; kt <= qt; kt++) {
        const int k0 = kt * 64;
        __syncthreads();

        #pragma unroll
        for (int u = 0; u < 8; u++) {
            int row = lrow + u*8;
            float4 k = *(const float4*)(Kg + (size_t)(k0+row)*D_MODEL + lcol);
            k.x = __uint_as_float(f2tf32(k.x));
            k.y = __uint_as_float(f2tf32(k.y));
            k.z = __uint_as_float(f2tf32(k.z));
            k.w = __uint_as_float(f2tf32(k.w));
            *(float4*)&sK[row*PK + lcol] = k;
        }
        float4 pv[8];
        #pragma unroll
        for (int u = 0; u < 8; u++) {
            int row = lrow + u*8;
            pv[u] = *(const float4*)(Vg + (size_t)(k0+row)*D_MODEL + lcol);
        }
        __syncthreads();

        float s[8][4];
        #pragma unroll
        for (int nf = 0; nf < 8; nf++)
            #pragma unroll
            for (int c = 0; c < 4; c++) s[nf][c] = 0.f;

        #pragma unroll
        for (int kb = 0; kb < 8; kb++) {
            #pragma unroll
            for (int nf = 0; nf < 8; nf++) {
                uint32_t bh2[2];
                int base = (nf*8+gr)*PK + kb*8 + tig;
                bh2[0] = __float_as_uint(sK[base]);
                bh2[1] = __float_as_uint(sK[base + 4]);
                mma_tf32(s[nf], qh[kb], bh2);
            }
        }

        if (kt == qt) {
            #pragma unroll
            for (int nf = 0; nf < 8; nf++) {
                int cl = nf*8 + 2*tig;
                if (cl   > r0l) s[nf][0] = -INFINITY;
                if (cl+1 > r0l) s[nf][1] = -INFINITY;
                if (cl   > r1l) s[nf][2] = -INFINITY;
                if (cl+1 > r1l) s[nf][3] = -INFINITY;
            }
        }

        #pragma unroll
        for (int u = 0; u < 8; u++) {
            int row = lrow + u*8;
            float4 v = pv[u];
            v.x = __uint_as_float(f2tf32(v.x));
            v.y = __uint_as_float(f2tf32(v.y));
            v.z = __uint_as_float(f2tf32(v.z));
            v.w = __uint_as_float(f2tf32(v.w));
            *(float4*)&sV[row*PVP + lcol] = v;
        }

        float ml0 = -INFINITY, ml1 = -INFINITY;
        #pragma unroll
        for (int nf = 0; nf < 8; nf++) {
            ml0 = fmaxf(ml0, fmaxf(s[nf][0], s[nf][1]));
            ml1 = fmaxf(ml1, fmaxf(s[nf][2], s[nf][3]));
        }
        ml0 = fmaxf(ml0, __shfl_xor_sync(0xffffffffu, ml0, 1));
        ml0 = fmaxf(ml0, __shfl_xor_sync(0xffffffffu, ml0, 2));
        ml1 = fmaxf(ml1, __shfl_xor_sync(0xffffffffu, ml1, 1));
        ml1 = fmaxf(ml1, __shfl_xor_sync(0xffffffffu, ml1, 2));

        float mn0 = fmaxf(m0, ml0), mn1 = fmaxf(m1, ml1);
        float al0 = __expf(m0 - mn0), al1 = __expf(m1 - mn1);
        float rs0 = 0.f, rs1 = 0.f;
        #pragma unroll
        for (int nf = 0; nf < 8; nf++) {
            float p0 = __expf(s[nf][0] - mn0);
            float p1 = __expf(s[nf][1] - mn0);
            float p2 = __expf(s[nf][2] - mn1);
            float p3 = __expf(s[nf][3] - mn1);
            s[nf][0] = p0; s[nf][1] = p1; s[nf][2] = p2; s[nf][3] = p3;
            rs0 += p0 + p1; rs1 += p2 + p3;
        }
        rs0 += __shfl_xor_sync(0xffffffffu, rs0, 1);
        rs0 += __shfl_xor_sync(0xffffffffu, rs0, 2);
        rs1 += __shfl_xor_sync(0xffffffffu, rs1, 1);
        rs1 += __shfl_xor_sync(0xffffffffu, rs1, 2);
        l0 = l0*al0 + rs0; m0 = mn0;
        l1 = l1*al1 + rs1; m1 = mn1;
        #pragma unroll
        for (int nf = 0; nf < 8; nf++) {
            acc[nf][0] *= al0; acc[nf][1] *= al0;
            acc[nf][2] *= al1; acc[nf][3] *= al1;
        }

        __syncthreads();

        #pragma unroll
        for (int nf = 0; nf < 8; nf++) {
            float h0 = __uint_as_float(f2tf32(s[nf][0]));
            float h1 = __uint_as_float(f2tf32(s[nf][1]));
            float h2 = __uint_as_float(f2tf32(s[nf][2]));
            float h3 = __uint_as_float(f2tf32(s[nf][3]));
            *(float2*)&sK[r0l*PK + nf*8 + 2*tig] = make_float2(h0, h1);
            *(float2*)&sK[r1l*PK + nf*8 + 2*tig] = make_float2(h2, h3);
        }
        __syncwarp();

        #pragma unroll
        for (int kb = 0; kb < 8; kb++) {
            uint32_t ah[4];
            ah[0] = __float_as_uint(sK[r0l*PK + kb*8 + tig]);
            ah[1] = __float_as_uint(sK[r1l*PK + kb*8 + tig]);
            ah[2] = __float_as_uint(sK[r0l*PK + kb*8 + tig + 4]);
            ah[3] = __float_as_uint(sK[r1l*PK + kb*8 + tig + 4]);
            #pragma unroll
            for (int nf = 0; nf < 8; nf++) {
                uint32_t bb[2];
                bb[0] = __float_as_uint(sV[(kb*8+tig)*PVP + nf*8 + gr]);
                bb[1] = __float_as_uint(sV[(kb*8+tig+4)*PVP + nf*8 + gr]);
                mma_tf32(acc[nf], ah, bb);
            }
        }
    }

    const float il0 = 1.0f / l0;
    const float il1 = 1.0f / l1;
    const int r0g = q0 + r0l;
    const int r1g = q0 + r1l;
    float* o0 = g_attn + (size_t)(b*SEQ + r0g)*D_MODEL + h*DHEAD;
    float* o1 = g_attn + (size_t)(b*SEQ + r1g)*D_MODEL + h*DHEAD;
    #pragma unroll
    for (int nf = 0; nf < 8; nf++) {
        *(float2*)(o0 + nf*8 + 2*tig) = make_float2(acc[nf][0]*il0, acc[nf][1]*il0);
        *(float2*)(o1 + nf*8 + 2*tig) = make_float2(acc[nf][2]*il1, acc[nf][3]*il1);
    }
}

// ---------------------------------------------------------------------------
extern "C" void kernel_launch(void* const* d_in, const int* in_sizes, int n_in,
                              void* d_out, int out_size)
{
    const float* X   = (const float*)d_in[0];
    const int*   pos = (const int*)  d_in[1];
    const float* wq  = (const float*)d_in[2];
    const float* wk  = (const float*)d_in[3];
    const float* wv  = (const float*)d_in[4];
    const float* wo  = (const float*)d_in[5];
    float* out = (float*)d_out;

    dim3 gQKV(D_MODEL/128, M_TOTAL/128, 3);          // (8, 32, 3)
    gemm_tf32_kernel<<<gQKV, 256>>>(X, wq, wk, wv, wo, pos, out, 0);

    dim3 gAttn(SEQ/64, BATCH*NHEAD);                 // (32, 32)
    attn_mma_kernel<<<gAttn, 128>>>();

    dim3 gOut(D_MODEL/128, M_TOTAL/128, 1);          // (8, 32)
    gemm_tf32_kernel<<<gOut, 256>>>(X, wq, wk, wv, wo, pos, out, 3);
}

// round 14
// speedup vs baseline: 1.2142x; 1.2142x over previous
#include <cuda_runtime.h>
#include <math.h>
#include <cstdint>

#define D_MODEL 1024
#define NHEAD   16
#define DHEAD   64
#define BATCH   2
#define SEQ     2048
#define M_TOTAL (BATCH*SEQ)

// Scratch (allocation-free rule: __device__ globals).
__device__ float g_q[M_TOTAL*D_MODEL];
__device__ float g_k[M_TOTAL*D_MODEL];
__device__ float g_v[M_TOTAL*D_MODEL];
__device__ float g_attn[M_TOTAL*D_MODEL];

__device__ __forceinline__ uint32_t f2tf32(float x) {
    uint32_t r; asm("cvt.rna.tf32.f32 %0, %1;" : "=r"(r) : "f"(x));
    return r;
}

__device__ __forceinline__ void mma_tf32(float c[4], const uint32_t a[4], const uint32_t b[2]) {
    asm volatile(
        "mma.sync.aligned.m16n8k8.row.col.f32.tf32.tf32.f32 "
        "{%0,%1,%2,%3}, {%4,%5,%6,%7}, {%8,%9}, {%0,%1,%2,%3};"
        : "+f"(c[0]), "+f"(c[1]), "+f"(c[2]), "+f"(c[3])
        : "r"(a[0]), "r"(a[1]), "r"(a[2]), "r"(a[3]), "r"(b[0]), "r"(b[1]));
}

// ---------------------------------------------------------------------------
// Pipelined tf32 mma.sync GEMM — R8 proven config (126 regs, 45% tensor).
// Single smem buffer, register prefetch of next k-tile, PITCH 36.
// ---------------------------------------------------------------------------
#define PITCH 36

__global__ void __launch_bounds__(256) gemm_tf32_kernel(
    const float* __restrict__ X,
    const float* __restrict__ Wq, const float* __restrict__ Wk,
    const float* __restrict__ Wv, const float* __restrict__ Wo,
    const int*   __restrict__ pos,
    float* __restrict__ dout,
    int mode_base)
{
    __shared__ __align__(16) uint32_t As[128*PITCH];
    __shared__ __align__(16) uint32_t Bs[128*PITCH];

    const int mode = mode_base + blockIdx.z;
    const float* A = (mode == 3) ? g_attn : X;
    const float* W = (mode == 0) ? Wq : (mode == 1) ? Wk : (mode == 2) ? Wv : Wo;
    float* out = (mode == 0) ? g_q : (mode == 1) ? g_k : (mode == 2) ? g_v : dout;
    const bool rope = (mode <= 1);

    const int tid  = threadIdx.x;
    const int warp = tid >> 5;
    const int lane = tid & 31;
    const int gr   = lane >> 2;
    const int tig  = lane & 3;
    const int wm   = warp & 3;
    const int wn   = warp >> 2;
    const int m0   = blockIdx.y * 128;
    const int n0   = blockIdx.x * 128;

    float acc[2][8][4];
    #pragma unroll
    for (int mf = 0; mf < 2; mf++)
        #pragma unroll
        for (int nf = 0; nf < 8; nf++)
            #pragma unroll
            for (int c = 0; c < 4; c++) acc[mf][nf][c] = 0.f;

    const float* Ap = A + (size_t)m0 * D_MODEL;
    const float* Wp = W + (size_t)n0 * D_MODEL;

    const int lrow = tid >> 3;
    const int lkq  = (tid & 7) << 2;

    float4 pa[4], pb[4];
    #pragma unroll
    for (int u = 0; u < 4; u++) {
        int row = lrow + u * 32;
        pa[u] = *(const float4*)(Ap + (size_t)row * D_MODEL + lkq);
        pb[u] = *(const float4*)(Wp + (size_t)row * D_MODEL + lkq);
    }

    for (int kt = 0; kt < 32; kt++) {
        #pragma unroll
        for (int u = 0; u < 4; u++) {
            int row = lrow + u * 32;
            uint4 ua = make_uint4(f2tf32(pa[u].x), f2tf32(pa[u].y), f2tf32(pa[u].z), f2tf32(pa[u].w));
            *(uint4*)&As[row * PITCH + lkq] = ua;
            uint4 ub = make_uint4(f2tf32(pb[u].x), f2tf32(pb[u].y), f2tf32(pb[u].z), f2tf32(pb[u].w));
            *(uint4*)&Bs[row * PITCH + lkq] = ub;
        }
        __syncthreads();

        if (kt < 31) {
            const int kn = (kt + 1) * 32;
            #pragma unroll
            for (int u = 0; u < 4; u++) {
                int row = lrow + u * 32;
                pa[u] = *(const float4*)(Ap + (size_t)row * D_MODEL + kn + lkq);
                pb[u] = *(const float4*)(Wp + (size_t)row * D_MODEL + kn + lkq);
            }
        }

        #pragma unroll
        for (int ks = 0; ks < 4; ks++) {
            const int kb = ks * 8;
            uint32_t b[8][2];
            #pragma unroll
            for (int nf = 0; nf < 8; nf++) {
                int n = wn*64 + nf*8 + gr;
                b[nf][0] = Bs[n * PITCH + kb + tig];
                b[nf][1] = Bs[n * PITCH + kb + tig + 4];
            }
            uint32_t a[2][4];
            #pragma unroll
            for (int mf = 0; mf < 2; mf++) {
                int m = wm*32 + mf*16 + gr;
                a[mf][0] = As[m * PITCH + kb + tig];
                a[mf][1] = As[(m+8) * PITCH + kb + tig];
                a[mf][2] = As[m * PITCH + kb + tig + 4];
                a[mf][3] = As[(m+8) * PITCH + kb + tig + 4];
            }
            #pragma unroll
            for (int mf = 0; mf < 2; mf++)
                #pragma unroll
                for (int nf = 0; nf < 8; nf++)
                    mma_tf32(acc[mf][nf], a[mf], b[nf]);
        }
        __syncthreads();
    }

    float invf[8];
    if (rope) {
        #pragma unroll
        for (int nf = 0; nf < 8; nf++) {
            int dh = (nf*8 + 2*tig) & 63;
            invf[nf] = 1.0f / powf(10000.0f, (float)dh * (1.0f/64.0f));
        }
    }

    #pragma unroll
    for (int mf = 0; mf < 2; mf++) {
        int m_lo = m0 + wm*32 + mf*16 + gr;
        int m_hi = m_lo + 8;
        float fp_lo = 0.f, fp_hi = 0.f;
        if (rope) {
            fp_lo = (float)pos[m_lo & (SEQ-1)];
            fp_hi = (float)pos[m_hi & (SEQ-1)];
        }
        #pragma unroll
        for (int nf = 0; nf < 8; nf++) {
            int n = n0 + wn*64 + nf*8 + 2*tig;
            float v0 = acc[mf][nf][0], v1 = acc[mf][nf][1];
            float v2 = acc[mf][nf][2], v3 = acc[mf][nf][3];
            if (rope) {
                float c0, s0, c1, s1;
                sincosf(fp_lo * invf[nf], &s0, &c0);
                sincosf(fp_hi * invf[nf], &s1, &c1);
                float r0 = v0*c0 - v1*s0, r1 = v1*c0 + v0*s0;
                float r2 = v2*c1 - v3*s1, r3 = v3*c1 + v2*s1;
                v0 = r0; v1 = r1; v2 = r2; v3 = r3;
            }
            *(float2*)(out + (size_t)m_lo * D_MODEL + n) = make_float2(v0, v1);
            *(float2*)(out + (size_t)m_hi * D_MODEL + n) = make_float2(v2, v3);
        }
    }
}

// ---------------------------------------------------------------------------
// Flash attention — R12 version (V gmem loads deferred past QK^T MMAs).
// 64 q-rows, 4 warps, 35.8KB static smem. QK^T 1-MMA, PV 1-MMA.
// ---------------------------------------------------------------------------
#define PK  68
#define PVP 72

__global__ void __launch_bounds__(128) attn_mma_kernel()
{
    __shared__ float sK[64*PK];   // K tile (pre-rounded tf32); reused as P tile
    __shared__ float sV[64*PVP];  // V tile (pre-rounded tf32)

    const int tid  = threadIdx.x;
    const int warp = tid >> 5;
    const int lane = tid & 31;
    const int gr   = lane >> 2;
    const int tig  = lane & 3;
    const int qt   = gridDim.x - 1 - blockIdx.x;   // longest tiles first
    const int bh   = blockIdx.y;
    const int q0   = qt * 64;
    const int b    = bh >> 4;
    const int h    = bh & 15;

    const float* Qg = g_q + (size_t)b*SEQ*D_MODEL + h*DHEAD;
    const float* Kg = g_k + (size_t)b*SEQ*D_MODEL + h*DHEAD;
    const float* Vg = g_v + (size_t)b*SEQ*D_MODEL + h*DHEAD;

    #pragma unroll
    for (int u = 0; u < 8; u++) {
        int f   = tid + u*128;
        int row = f >> 4;
        int c   = (f & 15) << 2;
        float4 q = *(const float4*)(Qg + (size_t)(q0+row)*D_MODEL + c);
        q.x *= 0.125f; q.y *= 0.125f; q.z *= 0.125f; q.w *= 0.125f;
        *(float4*)&sK[row*PK + c] = q;
    }
    __syncthreads();

    const int r0l = warp*16 + gr;
    const int r1l = r0l + 8;

    uint32_t qh[8][4];
    #pragma unroll
    for (int kb = 0; kb < 8; kb++) {
        qh[kb][0] = f2tf32(sK[r0l*PK + kb*8 + tig]);
        qh[kb][1] = f2tf32(sK[r1l*PK + kb*8 + tig]);
        qh[kb][2] = f2tf32(sK[r0l*PK + kb*8 + tig + 4]);
        qh[kb][3] = f2tf32(sK[r1l*PK + kb*8 + tig + 4]);
    }

    float m0 = -INFINITY, m1 = -INFINITY, l0 = 0.f, l1 = 0.f;
    float acc[8][4];
    #pragma unroll
    for (int nf = 0; nf < 8; nf++)
        #pragma unroll
        for (int c = 0; c < 4; c++) acc[nf][c] = 0.f;

    const int lrow = tid >> 4;         // 0..7 base row
    const int lcol = (tid & 15) << 2;  // 0..60

    for (int kt = 0; kt <= qt; kt++) {
        const int k0 = kt * 64;
        __syncthreads();  // prior P/V reads (or Q extraction) complete

        // K: load + round + STS
        #pragma unroll
        for (int u = 0; u < 8; u++) {
            int row = lrow + u*8;
            float4 k = *(const float4*)(Kg + (size_t)(k0+row)*D_MODEL + lcol);
            k.x = __uint_as_float(f2tf32(k.x));
            k.y = __uint_as_float(f2tf32(k.y));
            k.z = __uint_as_float(f2tf32(k.z));
            k.w = __uint_as_float(f2tf32(k.w));
            *(float4*)&sK[row*PK + lcol] = k;
        }
        // V: issue gmem loads now (STS deferred past QK^T MMAs)
        float4 pv[8];
        #pragma unroll
        for (int u = 0; u < 8; u++) {
            int row = lrow + u*8;
            pv[u] = *(const float4*)(Vg + (size_t)(k0+row)*D_MODEL + lcol);
        }
        __syncthreads();  // sK ready

        // S = Q @ K^T  (single MMA per fragment; V loads in flight)
        float s[8][4];
        #pragma unroll
        for (int nf = 0; nf < 8; nf++)
            #pragma unroll
            for (int c = 0; c < 4; c++) s[nf][c] = 0.f;

        #pragma unroll
        for (int kb = 0; kb < 8; kb++) {
            #pragma unroll
            for (int nf = 0; nf < 8; nf++) {
                uint32_t bh2[2];
                int base = (nf*8+gr)*PK + kb*8 + tig;
                bh2[0] = __float_as_uint(sK[base]);
                bh2[1] = __float_as_uint(sK[base + 4]);
                mma_tf32(s[nf], qh[kb], bh2);
            }
        }

        if (kt == qt) {
            #pragma unroll
            for (int nf = 0; nf < 8; nf++) {
                int cl = nf*8 + 2*tig;
                if (cl   > r0l) s[nf][0] = -INFINITY;
                if (cl+1 > r0l) s[nf][1] = -INFINITY;
                if (cl   > r1l) s[nf][2] = -INFINITY;
                if (cl+1 > r1l) s[nf][3] = -INFINITY;
            }
        }

        // V: round + STS (loads have had the whole QK^T phase to land)
        #pragma unroll
        for (int u = 0; u < 8; u++) {
            int row = lrow + u*8;
            float4 v = pv[u];
            v.x = __uint_as_float(f2tf32(v.x));
            v.y = __uint_as_float(f2tf32(v.y));
            v.z = __uint_as_float(f2tf32(v.z));
            v.w = __uint_as_float(f2tf32(v.w));
            *(float4*)&sV[row*PVP + lcol] = v;
        }

        // Online softmax
        float ml0 = -INFINITY, ml1 = -INFINITY;
        #pragma unroll
        for (int nf = 0; nf < 8; nf++) {
            ml0 = fmaxf(ml0, fmaxf(s[nf][0], s[nf][1]));
            ml1 = fmaxf(ml1, fmaxf(s[nf][2], s[nf][3]));
        }
        ml0 = fmaxf(ml0, __shfl_xor_sync(0xffffffffu, ml0, 1));
        ml0 = fmaxf(ml0, __shfl_xor_sync(0xffffffffu, ml0, 2));
        ml1 = fmaxf(ml1, __shfl_xor_sync(0xffffffffu, ml1, 1));
        ml1 = fmaxf(ml1, __shfl_xor_sync(0xffffffffu, ml1, 2));

        float mn0 = fmaxf(m0, ml0), mn1 = fmaxf(m1, ml1);
        float al0 = __expf(m0 - mn0), al1 = __expf(m1 - mn1);
        float rs0 = 0.f, rs1 = 0.f;
        #pragma unroll
        for (int nf = 0; nf < 8; nf++) {
            float p0 = __expf(s[nf][0] - mn0);
            float p1 = __expf(s[nf][1] - mn0);
            float p2 = __expf(s[nf][2] - mn1);
            float p3 = __expf(s[nf][3] - mn1);
            s[nf][0] = p0; s[nf][1] = p1; s[nf][2] = p2; s[nf][3] = p3;
            rs0 += p0 + p1; rs1 += p2 + p3;
        }
        rs0 += __shfl_xor_sync(0xffffffffu, rs0, 1);
        rs0 += __shfl_xor_sync(0xffffffffu, rs0, 2);
        rs1 += __shfl_xor_sync(0xffffffffu, rs1, 1);
        rs1 += __shfl_xor_sync(0xffffffffu, rs1, 2);
        l0 = l0*al0 + rs0; m0 = mn0;
        l1 = l1*al1 + rs1; m1 = mn1;
        #pragma unroll
        for (int nf = 0; nf < 8; nf++) {
            acc[nf][0] *= al0; acc[nf][1] *= al0;
            acc[nf][2] *= al1; acc[nf][3] *= al1;
        }

        __syncthreads(); // all warps done reading K; sV fully written

        // Store P tf32-rounded into sK region (each warp its own 16 rows)
        #pragma unroll
        for (int nf = 0; nf < 8; nf++) {
            float h0 = __uint_as_float(f2tf32(s[nf][0]));
            float h1 = __uint_as_float(f2tf32(s[nf][1]));
            float h2 = __uint_as_float(f2tf32(s[nf][2]));
            float h3 = __uint_as_float(f2tf32(s[nf][3]));
            *(float2*)&sK[r0l*PK + nf*8 + 2*tig] = make_float2(h0, h1);
            *(float2*)&sK[r1l*PK + nf*8 + 2*tig] = make_float2(h2, h3);
        }
        __syncwarp();

        // O += P @ V  (single MMA)
        #pragma unroll
        for (int kb = 0; kb < 8; kb++) {
            uint32_t ah[4];
            ah[0] = __float_as_uint(sK[r0l*PK + kb*8 + tig]);
            ah[1] = __float_as_uint(sK[r1l*PK + kb*8 + tig]);
            ah[2] = __float_as_uint(sK[r0l*PK + kb*8 + tig + 4]);
            ah[3] = __float_as_uint(sK[r1l*PK + kb*8 + tig + 4]);
            #pragma unroll
            for (int nf = 0; nf < 8; nf++) {
                uint32_t bb[2];
                bb[0] = __float_as_uint(sV[(kb*8+tig)*PVP + nf*8 + gr]);
                bb[1] = __float_as_uint(sV[(kb*8+tig+4)*PVP + nf*8 + gr]);
                mma_tf32(acc[nf], ah, bb);
            }
        }
    }

    const float il0 = 1.0f / l0;
    const float il1 = 1.0f / l1;
    const int r0g = q0 + r0l;
    const int r1g = q0 + r1l;
    float* o0 = g_attn + (size_t)(b*SEQ + r0g)*D_MODEL + h*DHEAD;
    float* o1 = g_attn + (size_t)(b*SEQ + r1g)*D_MODEL + h*DHEAD;
    #pragma unroll
    for (int nf = 0; nf < 8; nf++) {
        *(float2*)(o0 + nf*8 + 2*tig) = make_float2(acc[nf][0]*il0, acc[nf][1]*il0);
        *(float2*)(o1 + nf*8 + 2*tig) = make_float2(acc[nf][2]*il1, acc[nf][3]*il1);
    }
}

// ---------------------------------------------------------------------------
extern "C" void kernel_launch(void* const* d_in, const int* in_sizes, int n_in,
                              void* d_out, int out_size)
{
    const float* X   = (const float*)d_in[0];
    const int*   pos = (const int*)  d_in[1];
    const float* wq  = (const float*)d_in[2];
    const float* wk  = (const float*)d_in[3];
    const float* wv  = (const float*)d_in[4];
    const float* wo  = (const float*)d_in[5];
    float* out = (float*)d_out;

    dim3 gQKV(D_MODEL/128, M_TOTAL/128, 3);          // (8, 32, 3)
    gemm_tf32_kernel<<<gQKV, 256>>>(X, wq, wk, wv, wo, pos, out, 0);

    dim3 gAttn(SEQ/64, BATCH*NHEAD);                 // (32, 32)
    attn_mma_kernel<<<gAttn, 128>>>();

    dim3 gOut(D_MODEL/128, M_TOTAL/128, 1);          // (8, 32)
    gemm_tf32_kernel<<<gOut, 256>>>(X, wq, wk, wv, wo, pos, out, 3);
}

// round 15
// speedup vs baseline: 1.2164x; 1.0018x over previous
#include <cuda_runtime.h>
#include <math.h>
#include <cstdint>

#define D_MODEL 1024
#define NHEAD   16
#define DHEAD   64
#define BATCH   2
#define SEQ     2048
#define M_TOTAL (BATCH*SEQ)

// Scratch (allocation-free rule: __device__ globals).
__device__ float g_q[M_TOTAL*D_MODEL];
__device__ float g_k[M_TOTAL*D_MODEL];
__device__ float g_v[M_TOTAL*D_MODEL];
__device__ float g_attn[M_TOTAL*D_MODEL];

__device__ __forceinline__ uint32_t f2tf32(float x) {
    uint32_t r; asm("cvt.rna.tf32.f32 %0, %1;" : "=r"(r) : "f"(x));
    return r;
}

__device__ __forceinline__ void mma_tf32(float c[4], const uint32_t a[4], const uint32_t b[2]) {
    asm volatile(
        "mma.sync.aligned.m16n8k8.row.col.f32.tf32.tf32.f32 "
        "{%0,%1,%2,%3}, {%4,%5,%6,%7}, {%8,%9}, {%0,%1,%2,%3};"
        : "+f"(c[0]), "+f"(c[1]), "+f"(c[2]), "+f"(c[3])
        : "r"(a[0]), "r"(a[1]), "r"(a[2]), "r"(a[3]), "r"(b[0]), "r"(b[1]));
}

// ---------------------------------------------------------------------------
// Pipelined tf32 mma.sync GEMM — R8 proven config (126 regs, 45% tensor).
// ---------------------------------------------------------------------------
#define PITCH 36

__global__ void __launch_bounds__(256) gemm_tf32_kernel(
    const float* __restrict__ X,
    const float* __restrict__ Wq, const float* __restrict__ Wk,
    const float* __restrict__ Wv, const float* __restrict__ Wo,
    const int*   __restrict__ pos,
    float* __restrict__ dout,
    int mode_base)
{
    __shared__ __align__(16) uint32_t As[128*PITCH];
    __shared__ __align__(16) uint32_t Bs[128*PITCH];

    const int mode = mode_base + blockIdx.z;
    const float* A = (mode == 3) ? g_attn : X;
    const float* W = (mode == 0) ? Wq : (mode == 1) ? Wk : (mode == 2) ? Wv : Wo;
    float* out = (mode == 0) ? g_q : (mode == 1) ? g_k : (mode == 2) ? g_v : dout;
    const bool rope = (mode <= 1);

    const int tid  = threadIdx.x;
    const int warp = tid >> 5;
    const int lane = tid & 31;
    const int gr   = lane >> 2;
    const int tig  = lane & 3;
    const int wm   = warp & 3;
    const int wn   = warp >> 2;
    const int m0   = blockIdx.y * 128;
    const int n0   = blockIdx.x * 128;

    float acc[2][8][4];
    #pragma unroll
    for (int mf = 0; mf < 2; mf++)
        #pragma unroll
        for (int nf = 0; nf < 8; nf++)
            #pragma unroll
            for (int c = 0; c < 4; c++) acc[mf][nf][c] = 0.f;

    const float* Ap = A + (size_t)m0 * D_MODEL;
    const float* Wp = W + (size_t)n0 * D_MODEL;

    const int lrow = tid >> 3;
    const int lkq  = (tid & 7) << 2;

    float4 pa[4], pb[4];
    #pragma unroll
    for (int u = 0; u < 4; u++) {
        int row = lrow + u * 32;
        pa[u] = *(const float4*)(Ap + (size_t)row * D_MODEL + lkq);
        pb[u] = *(const float4*)(Wp + (size_t)row * D_MODEL + lkq);
    }

    for (int kt = 0; kt < 32; kt++) {
        #pragma unroll
        for (int u = 0; u < 4; u++) {
            int row = lrow + u * 32;
            uint4 ua = make_uint4(f2tf32(pa[u].x), f2tf32(pa[u].y), f2tf32(pa[u].z), f2tf32(pa[u].w));
            *(uint4*)&As[row * PITCH + lkq] = ua;
            uint4 ub = make_uint4(f2tf32(pb[u].x), f2tf32(pb[u].y), f2tf32(pb[u].z), f2tf32(pb[u].w));
            *(uint4*)&Bs[row * PITCH + lkq] = ub;
        }
        __syncthreads();

        if (kt < 31) {
            const int kn = (kt + 1) * 32;
            #pragma unroll
            for (int u = 0; u < 4; u++) {
                int row = lrow + u * 32;
                pa[u] = *(const float4*)(Ap + (size_t)row * D_MODEL + kn + lkq);
                pb[u] = *(const float4*)(Wp + (size_t)row * D_MODEL + kn + lkq);
            }
        }

        #pragma unroll
        for (int ks = 0; ks < 4; ks++) {
            const int kb = ks * 8;
            uint32_t b[8][2];
            #pragma unroll
            for (int nf = 0; nf < 8; nf++) {
                int n = wn*64 + nf*8 + gr;
                b[nf][0] = Bs[n * PITCH + kb + tig];
                b[nf][1] = Bs[n * PITCH + kb + tig + 4];
            }
            uint32_t a[2][4];
            #pragma unroll
            for (int mf = 0; mf < 2; mf++) {
                int m = wm*32 + mf*16 + gr;
                a[mf][0] = As[m * PITCH + kb + tig];
                a[mf][1] = As[(m+8) * PITCH + kb + tig];
                a[mf][2] = As[m * PITCH + kb + tig + 4];
                a[mf][3] = As[(m+8) * PITCH + kb + tig + 4];
            }
            #pragma unroll
            for (int mf = 0; mf < 2; mf++)
                #pragma unroll
                for (int nf = 0; nf < 8; nf++)
                    mma_tf32(acc[mf][nf], a[mf], b[nf]);
        }
        __syncthreads();
    }

    float invf[8];
    if (rope) {
        #pragma unroll
        for (int nf = 0; nf < 8; nf++) {
            int dh = (nf*8 + 2*tig) & 63;
            invf[nf] = 1.0f / powf(10000.0f, (float)dh * (1.0f/64.0f));
        }
    }

    #pragma unroll
    for (int mf = 0; mf < 2; mf++) {
        int m_lo = m0 + wm*32 + mf*16 + gr;
        int m_hi = m_lo + 8;
        float fp_lo = 0.f, fp_hi = 0.f;
        if (rope) {
            fp_lo = (float)pos[m_lo & (SEQ-1)];
            fp_hi = (float)pos[m_hi & (SEQ-1)];
        }
        #pragma unroll
        for (int nf = 0; nf < 8; nf++) {
            int n = n0 + wn*64 + nf*8 + 2*tig;
            float v0 = acc[mf][nf][0], v1 = acc[mf][nf][1];
            float v2 = acc[mf][nf][2], v3 = acc[mf][nf][3];
            if (rope) {
                float c0, s0, c1, s1;
                sincosf(fp_lo * invf[nf], &s0, &c0);
                sincosf(fp_hi * invf[nf], &s1, &c1);
                float r0 = v0*c0 - v1*s0, r1 = v1*c0 + v0*s0;
                float r2 = v2*c1 - v3*s1, r3 = v3*c1 + v2*s1;
                v0 = r0; v1 = r1; v2 = r2; v3 = r3;
            }
            *(float2*)(out + (size_t)m_lo * D_MODEL + n) = make_float2(v0, v1);
            *(float2*)(out + (size_t)m_hi * D_MODEL + n) = make_float2(v2, v3);
        }
    }
}

// ---------------------------------------------------------------------------
// Flash attention — direct V load+STS (no reg deferral) with
// __launch_bounds__(128, 4): regs capped at 128 -> 4 CTAs/SM (16 warps).
// QK^T 1-MMA, PV 1-MMA. 35.8KB static smem.
// ---------------------------------------------------------------------------
#define PK  68
#define PVP 72

__global__ void __launch_bounds__(128, 4) attn_mma_kernel()
{
    __shared__ float sK[64*PK];   // K tile (pre-rounded tf32); reused as P tile
    __shared__ float sV[64*PVP];  // V tile (pre-rounded tf32)

    const int tid  = threadIdx.x;
    const int warp = tid >> 5;
    const int lane = tid & 31;
    const int gr   = lane >> 2;
    const int tig  = lane & 3;
    const int qt   = gridDim.x - 1 - blockIdx.x;   // longest tiles first
    const int bh   = blockIdx.y;
    const int q0   = qt * 64;
    const int b    = bh >> 4;
    const int h    = bh & 15;

    const float* Qg = g_q + (size_t)b*SEQ*D_MODEL + h*DHEAD;
    const float* Kg = g_k + (size_t)b*SEQ*D_MODEL + h*DHEAD;
    const float* Vg = g_v + (size_t)b*SEQ*D_MODEL + h*DHEAD;

    #pragma unroll
    for (int u = 0; u < 8; u++) {
        int f   = tid + u*128;
        int row = f >> 4;
        int c   = (f & 15) << 2;
        float4 q = *(const float4*)(Qg + (size_t)(q0+row)*D_MODEL + c);
        q.x *= 0.125f; q.y *= 0.125f; q.z *= 0.125f; q.w *= 0.125f;
        *(float4*)&sK[row*PK + c] = q;
    }
    __syncthreads();

    const int r0l = warp*16 + gr;
    const int r1l = r0l + 8;

    uint32_t qh[8][4];
    #pragma unroll
    for (int kb = 0; kb < 8; kb++) {
        qh[kb][0] = f2tf32(sK[r0l*PK + kb*8 + tig]);
        qh[kb][1] = f2tf32(sK[r1l*PK + kb*8 + tig]);
        qh[kb][2] = f2tf32(sK[r0l*PK + kb*8 + tig + 4]);
        qh[kb][3] = f2tf32(sK[r1l*PK + kb*8 + tig + 4]);
    }

    float m0 = -INFINITY, m1 = -INFINITY, l0 = 0.f, l1 = 0.f;
    float acc[8][4];
    #pragma unroll
    for (int nf = 0; nf < 8; nf++)
        #pragma unroll
        for (int c = 0; c < 4; c++) acc[nf][c] = 0.f;

    const int lrow = tid >> 4;         // 0..7 base row
    const int lcol = (tid & 15) << 2;  // 0..60

    for (int kt = 0; kt <= qt; kt++) {
        const int k0 = kt * 64;
        __syncthreads();  // prior P/V reads (or Q extraction) complete

        // K and V: load + round + STS (interleaved, no reg buffering)
        #pragma unroll
        for (int u = 0; u < 8; u++) {
            int row = lrow + u*8;
            float4 k = *(const float4*)(Kg + (size_t)(k0+row)*D_MODEL + lcol);
            k.x = __uint_as_float(f2tf32(k.x));
            k.y = __uint_as_float(f2tf32(k.y));
            k.z = __uint_as_float(f2tf32(k.z));
            k.w = __uint_as_float(f2tf32(k.w));
            *(float4*)&sK[row*PK + lcol] = k;
            float4 v = *(const float4*)(Vg + (size_t)(k0+row)*D_MODEL + lcol);
            v.x = __uint_as_float(f2tf32(v.x));
            v.y = __uint_as_float(f2tf32(v.y));
            v.z = __uint_as_float(f2tf32(v.z));
            v.w = __uint_as_float(f2tf32(v.w));
            *(float4*)&sV[row*PVP + lcol] = v;
        }
        __syncthreads();

        // S = Q @ K^T  (single MMA per fragment)
        float s[8][4];
        #pragma unroll
        for (int nf = 0; nf < 8; nf++)
            #pragma unroll
            for (int c = 0; c < 4; c++) s[nf][c] = 0.f;

        #pragma unroll
        for (int kb = 0; kb < 8; kb++) {
            #pragma unroll
            for (int nf = 0; nf < 8; nf++) {
                uint32_t bh2[2];
                int base = (nf*8+gr)*PK + kb*8 + tig;
                bh2[0] = __float_as_uint(sK[base]);
                bh2[1] = __float_as_uint(sK[base + 4]);
                mma_tf32(s[nf], qh[kb], bh2);
            }
        }

        if (kt == qt) {
            #pragma unroll
            for (int nf = 0; nf < 8; nf++) {
                int cl = nf*8 + 2*tig;
                if (cl   > r0l) s[nf][0] = -INFINITY;
                if (cl+1 > r0l) s[nf][1] = -INFINITY;
                if (cl   > r1l) s[nf][2] = -INFINITY;
                if (cl+1 > r1l) s[nf][3] = -INFINITY;
            }
        }

        // Online softmax
        float ml0 = -INFINITY, ml1 = -INFINITY;
        #pragma unroll
        for (int nf = 0; nf < 8; nf++) {
            ml0 = fmaxf(ml0, fmaxf(s[nf][0], s[nf][1]));
            ml1 = fmaxf(ml1, fmaxf(s[nf][2], s[nf][3]));
        }
        ml0 = fmaxf(ml0, __shfl_xor_sync(0xffffffffu, ml0, 1));
        ml0 = fmaxf(ml0, __shfl_xor_sync(0xffffffffu, ml0, 2));
        ml1 = fmaxf(ml1, __shfl_xor_sync(0xffffffffu, ml1, 1));
        ml1 = fmaxf(ml1, __shfl_xor_sync(0xffffffffu, ml1, 2));

        float mn0 = fmaxf(m0, ml0), mn1 = fmaxf(m1, ml1);
        float al0 = __expf(m0 - mn0), al1 = __expf(m1 - mn1);
        float rs0 = 0.f, rs1 = 0.f;
        #pragma unroll
        for (int nf = 0; nf < 8; nf++) {
            float p0 = __expf(s[nf][0] - mn0);
            float p1 = __expf(s[nf][1] - mn0);
            float p2 = __expf(s[nf][2] - mn1);
            float p3 = __expf(s[nf][3] - mn1);
            s[nf][0] = p0; s[nf][1] = p1; s[nf][2] = p2; s[nf][3] = p3;
            rs0 += p0 + p1; rs1 += p2 + p3;
        }
        rs0 += __shfl_xor_sync(0xffffffffu, rs0, 1);
        rs0 += __shfl_xor_sync(0xffffffffu, rs0, 2);
        rs1 += __shfl_xor_sync(0xffffffffu, rs1, 1);
        rs1 += __shfl_xor_sync(0xffffffffu, rs1, 2);
        l0 = l0*al0 + rs0; m0 = mn0;
        l1 = l1*al1 + rs1; m1 = mn1;
        #pragma unroll
        for (int nf = 0; nf < 8; nf++) {
            acc[nf][0] *= al0; acc[nf][1] *= al0;
            acc[nf][2] *= al1; acc[nf][3] *= al1;
        }

        __syncthreads(); // all warps done reading K before P overwrites

        // Store P tf32-rounded into sK region (each warp its own 16 rows)
        #pragma unroll
        for (int nf = 0; nf < 8; nf++) {
            float h0 = __uint_as_float(f2tf32(s[nf][0]));
            float h1 = __uint_as_float(f2tf32(s[nf][1]));
            float h2 = __uint_as_float(f2tf32(s[nf][2]));
            float h3 = __uint_as_float(f2tf32(s[nf][3]));
            *(float2*)&sK[r0l*PK + nf*8 + 2*tig] = make_float2(h0, h1);
            *(float2*)&sK[r1l*PK + nf*8 + 2*tig] = make_float2(h2, h3);
        }
        __syncwarp();

        // O += P @ V  (single MMA)
        #pragma unroll
        for (int kb = 0; kb < 8; kb++) {
            uint32_t ah[4];
            ah[0] = __float_as_uint(sK[r0l*PK + kb*8 + tig]);
            ah[1] = __float_as_uint(sK[r1l*PK + kb*8 + tig]);
            ah[2] = __float_as_uint(sK[r0l*PK + kb*8 + tig + 4]);
            ah[3] = __float_as_uint(sK[r1l*PK + kb*8 + tig + 4]);
            #pragma unroll
            for (int nf = 0; nf < 8; nf++) {
                uint32_t bb[2];
                bb[0] = __float_as_uint(sV[(kb*8+tig)*PVP + nf*8 + gr]);
                bb[1] = __float_as_uint(sV[(kb*8+tig+4)*PVP + nf*8 + gr]);
                mma_tf32(acc[nf], ah, bb);
            }
        }
    }

    const float il0 = 1.0f / l0;
    const float il1 = 1.0f / l1;
    const int r0g = q0 + r0l;
    const int r1g = q0 + r1l;
    float* o0 = g_attn + (size_t)(b*SEQ + r0g)*D_MODEL + h*DHEAD;
    float* o1 = g_attn + (size_t)(b*SEQ + r1g)*D_MODEL + h*DHEAD;
    #pragma unroll
    for (int nf = 0; nf < 8; nf++) {
        *(float2*)(o0 + nf*8 + 2*tig) = make_float2(acc[nf][0]*il0, acc[nf][1]*il0);
        *(float2*)(o1 + nf*8 + 2*tig) = make_float2(acc[nf][2]*il1, acc[nf][3]*il1);
    }
}

// ---------------------------------------------------------------------------
extern "C" void kernel_launch(void* const* d_in, const int* in_sizes, int n_in,
                              void* d_out, int out_size)
{
    const float* X   = (const float*)d_in[0];
    const int*   pos = (const int*)  d_in[1];
    const float* wq  = (const float*)d_in[2];
    const float* wk  = (const float*)d_in[3];
    const float* wv  = (const float*)d_in[4];
    const float* wo  = (const float*)d_in[5];
    float* out = (float*)d_out;

    dim3 gQKV(D_MODEL/128, M_TOTAL/128, 3);          // (8, 32, 3)
    gemm_tf32_kernel<<<gQKV, 256>>>(X, wq, wk, wv, wo, pos, out, 0);

    dim3 gAttn(SEQ/64, BATCH*NHEAD);                 // (32, 32)
    attn_mma_kernel<<<gAttn, 128>>>();

    dim3 gOut(D_MODEL/128, M_TOTAL/128, 1);          // (8, 32)
    gemm_tf32_kernel<<<gOut, 256>>>(X, wq, wk, wv, wo, pos, out, 3);
}